// round 3
// baseline (speedup 1.0000x reference)
#include <cuda_runtime.h>

#define D 128
#define H 64
#define NMAX 100032
#define EMAX 1600000
#define FULL 0xffffffffu

// ---------------- scratch (static device globals; no allocations) -------------
__device__ float g_weights[NMAX];
__device__ int   g_deg[NMAX];
__device__ int   g_rowoff[NMAX + 1];
__device__ int   g_cursor[NMAX];
__device__ int   g_csrcol[EMAX];
__device__ int   g_partials[256];
__device__ int   g_is64;

// ---------------- dtype detection (1 warp) -------------------------------------
__global__ void k_detect(const void* __restrict__ ei, int E, int N) {
    const long long* e64 = (const long long*)ei;
    int lane = threadIdx.x;
    int ok = 1;
    if (lane < E) {
        long long v = e64[lane];
        ok = (v >= 0 && v < (long long)N) ? 1 : 0;
    }
    unsigned m = __ballot_sync(FULL, ok);
    if (lane == 0) g_is64 = (m == FULL) ? 1 : 0;
}

__device__ __forceinline__ int edge_at(const void* ei, size_t idx, int is64, int N) {
    long long v = is64 ? ((const long long*)ei)[idx] : (long long)((const int*)ei)[idx];
    if (v < 0) v = 0;
    if (v >= N) v = N - 1;
    return (int)v;
}

__global__ void k_zero(int N) {
    int i = blockIdx.x * blockDim.x + threadIdx.x;
    if (i < N) g_deg[i] = 0;
}

// ---------------- gate: weights = sigmoid(tanh(x@Wsim+bsim)@wvec + bvec) ------
__global__ void k_gate(const float4* __restrict__ x4, const float* __restrict__ Wsim,
                       const float* __restrict__ bsim, const float* __restrict__ wvec,
                       const float* __restrict__ bvec, int N) {
    __shared__ float sW[D * H];
    __shared__ float sb[H], sv[H];
    int tid = threadIdx.x;
    for (int i = tid; i < D * H; i += blockDim.x) sW[i] = Wsim[i];
    if (tid < H) { sb[tid] = bsim[tid]; sv[tid] = wvec[tid]; }
    __syncthreads();
    float bv = bvec[0];
    int lane = tid & 31, wp = tid >> 5;
    int gw = blockIdx.x * (blockDim.x >> 5) + wp;
    int nw = gridDim.x * (blockDim.x >> 5);
    int ngroups = (N + 3) >> 2;
    for (int g = gw; g < ngroups; g += nw) {
        int n0 = g * 4;
        float4 xv[4]; float a0[4], a1[4];
        #pragma unroll
        for (int t = 0; t < 4; t++) {
            int n = n0 + t;
            xv[t] = (n < N) ? x4[(size_t)n * 32 + lane] : make_float4(0.f, 0.f, 0.f, 0.f);
            a0[t] = sb[lane]; a1[t] = sb[lane + 32];
        }
        #pragma unroll 8
        for (int kk = 0; kk < 32; kk++) {
            float w00 = sW[(4 * kk + 0) * H + lane], w01 = sW[(4 * kk + 0) * H + lane + 32];
            float w10 = sW[(4 * kk + 1) * H + lane], w11 = sW[(4 * kk + 1) * H + lane + 32];
            float w20 = sW[(4 * kk + 2) * H + lane], w21 = sW[(4 * kk + 2) * H + lane + 32];
            float w30 = sW[(4 * kk + 3) * H + lane], w31 = sW[(4 * kk + 3) * H + lane + 32];
            #pragma unroll
            for (int t = 0; t < 4; t++) {
                float bx = __shfl_sync(FULL, xv[t].x, kk);
                float by = __shfl_sync(FULL, xv[t].y, kk);
                float bz = __shfl_sync(FULL, xv[t].z, kk);
                float bw = __shfl_sync(FULL, xv[t].w, kk);
                a0[t] += bx * w00 + by * w10 + bz * w20 + bw * w30;
                a1[t] += bx * w01 + by * w11 + bz * w21 + bw * w31;
            }
        }
        #pragma unroll
        for (int t = 0; t < 4; t++) {
            float h0 = tanhf(a0[t]), h1 = tanhf(a1[t]);
            float s = h0 * sv[lane] + h1 * sv[lane + 32];
            #pragma unroll
            for (int o = 16; o > 0; o >>= 1) s += __shfl_xor_sync(FULL, s, o);
            if (lane == 0 && n0 + t < N)
                g_weights[n0 + t] = 1.f / (1.f + __expf(-(s + bv)));
        }
    }
}

// ---------------- CSR build ----------------------------------------------------
__global__ void k_hist(const void* __restrict__ ei, int E, int N) {
    int is64 = g_is64;
    int i = blockIdx.x * blockDim.x + threadIdx.x;
    int stride = gridDim.x * blockDim.x;
    for (; i < E; i += stride) atomicAdd(&g_deg[edge_at(ei, i, is64, N)], 1);
}

__global__ void k_scan1(int N) {
    int i = blockIdx.x * 1024 + threadIdx.x;
    int v = (i < N) ? g_deg[i] : 0;
    #pragma unroll
    for (int o = 16; o > 0; o >>= 1) v += __shfl_xor_sync(FULL, v, o);
    __shared__ int ws[32];
    int lane = threadIdx.x & 31, w = threadIdx.x >> 5;
    if (lane == 0) ws[w] = v;
    __syncthreads();
    if (w == 0) {
        int s = ws[lane];
        #pragma unroll
        for (int o = 16; o > 0; o >>= 1) s += __shfl_xor_sync(FULL, s, o);
        if (lane == 0) g_partials[blockIdx.x] = s;
    }
}

__global__ void k_scan2(int nblk, int N, int E) {
    __shared__ int s[128];
    int tid = threadIdx.x;
    int v = (tid < nblk) ? g_partials[tid] : 0;
    s[tid] = v;
    __syncthreads();
    for (int o = 1; o < 128; o <<= 1) {
        int t = 0;
        if (tid >= o) t = s[tid - o];
        __syncthreads();
        s[tid] += t;
        __syncthreads();
    }
    if (tid < nblk) g_partials[tid] = s[tid] - v;
    if (tid == 0) g_rowoff[N] = E;
}

__global__ void k_scan3(int N) {
    int i = blockIdx.x * 1024 + threadIdx.x;
    int lane = threadIdx.x & 31, w = threadIdx.x >> 5;
    int v = (i < N) ? g_deg[i] : 0;
    int s = v;
    #pragma unroll
    for (int o = 1; o < 32; o <<= 1) {
        int t = __shfl_up_sync(FULL, s, o);
        if (lane >= o) s += t;
    }
    __shared__ int ws[32];
    if (lane == 31) ws[w] = s;
    __syncthreads();
    if (w == 0) {
        int t2 = ws[lane];
        #pragma unroll
        for (int o = 1; o < 32; o <<= 1) {
            int u = __shfl_up_sync(FULL, t2, o);
            if (lane >= o) t2 += u;
        }
        ws[lane] = t2;
    }
    __syncthreads();
    int excl = s - v + ((w > 0) ? ws[w - 1] : 0) + g_partials[blockIdx.x];
    if (i < N) { g_rowoff[i] = excl; g_cursor[i] = excl; }
}

__global__ void k_fill(const void* __restrict__ ei, int E, int N) {
    int is64 = g_is64;
    int i = blockIdx.x * blockDim.x + threadIdx.x;
    int stride = gridDim.x * blockDim.x;
    for (; i < E; i += stride) {
        int r = edge_at(ei, i, is64, N);
        int c = edge_at(ei, (size_t)E + i, is64, N);
        int pos = atomicAdd(&g_cursor[r], 1);
        if (pos >= 0 && pos < EMAX) g_csrcol[pos] = c;
    }
}

// ---------------- FUSED: gather + MLP1 + MLP2 + residual -----------------------
// One warp handles 4 consecutive nodes. The gather accumulator (float4 per lane)
// is directly the MLP1 input; MLP1's per-lane outputs are directly the MLP2
// shuffle sources. No intermediate global traffic.
__global__ void k_fused(const float4* __restrict__ x4,
                        const float* __restrict__ W1, const float* __restrict__ b1,
                        const float* __restrict__ W2, const float* __restrict__ b2,
                        float4* __restrict__ out4, int N) {
    extern __shared__ float sm[];
    float*  sW1 = sm;                                  // [D*H]  = 8192 floats
    float4* sW2 = (float4*)(sm + D * H);               // [H*32] = 8192 floats
    float*  sb1 = sm + 2 * D * H;                      // [64]
    float4* sb2 = (float4*)(sm + 2 * D * H + H);       // [32] float4

    int tid = threadIdx.x;
    for (int i = tid; i < D * H; i += blockDim.x) sW1[i] = W1[i];
    float* sW2f = (float*)sW2;
    for (int i = tid; i < H * D; i += blockDim.x) sW2f[i] = W2[i];
    if (tid < H) sb1[tid] = b1[tid];
    if (tid < 32) sb2[tid] = ((const float4*)b2)[tid];
    __syncthreads();

    int lane = tid & 31, wp = tid >> 5;
    int gw = blockIdx.x * (blockDim.x >> 5) + wp;
    int nw = gridDim.x * (blockDim.x >> 5);
    int ngroups = (N + 3) >> 2;

    for (int g = gw; g < ngroups; g += nw) {
        int n0 = g * 4;

        // ---- gather phase: acc[t] = sum_{edges of node n0+t} w[col] * x[col]
        float4 acc[4];
        #pragma unroll
        for (int t = 0; t < 4; t++) {
            acc[t] = make_float4(0.f, 0.f, 0.f, 0.f);
            int n = n0 + t;
            if (n >= N) continue;
            int s = g_rowoff[n], e = g_rowoff[n + 1];
            int p = s;
            for (; p + 4 <= e; p += 4) {
                int c0 = g_csrcol[p], c1 = g_csrcol[p + 1];
                int c2 = g_csrcol[p + 2], c3 = g_csrcol[p + 3];
                float w0 = g_weights[c0], w1 = g_weights[c1];
                float w2 = g_weights[c2], w3 = g_weights[c3];
                float4 v0 = x4[(size_t)c0 * 32 + lane];
                float4 v1 = x4[(size_t)c1 * 32 + lane];
                float4 v2 = x4[(size_t)c2 * 32 + lane];
                float4 v3 = x4[(size_t)c3 * 32 + lane];
                acc[t].x += v0.x * w0 + v1.x * w1 + v2.x * w2 + v3.x * w3;
                acc[t].y += v0.y * w0 + v1.y * w1 + v2.y * w2 + v3.y * w3;
                acc[t].z += v0.z * w0 + v1.z * w1 + v2.z * w2 + v3.z * w3;
                acc[t].w += v0.w * w0 + v1.w * w1 + v2.w * w2 + v3.w * w3;
            }
            for (; p < e; p++) {
                int c = g_csrcol[p];
                float w = g_weights[c];
                float4 v = x4[(size_t)c * 32 + lane];
                acc[t].x += v.x * w; acc[t].y += v.y * w;
                acc[t].z += v.z * w; acc[t].w += v.w * w;
            }
        }

        // ---- MLP1: a = relu(readout @ W1 + b1), outputs per lane: a0=h[lane], a1=h[lane+32]
        float a0[4], a1[4];
        #pragma unroll
        for (int t = 0; t < 4; t++) { a0[t] = sb1[lane]; a1[t] = sb1[lane + 32]; }
        #pragma unroll 8
        for (int kk = 0; kk < 32; kk++) {
            float w00 = sW1[(4 * kk + 0) * H + lane], w01 = sW1[(4 * kk + 0) * H + lane + 32];
            float w10 = sW1[(4 * kk + 1) * H + lane], w11 = sW1[(4 * kk + 1) * H + lane + 32];
            float w20 = sW1[(4 * kk + 2) * H + lane], w21 = sW1[(4 * kk + 2) * H + lane + 32];
            float w30 = sW1[(4 * kk + 3) * H + lane], w31 = sW1[(4 * kk + 3) * H + lane + 32];
            #pragma unroll
            for (int t = 0; t < 4; t++) {
                float bx = __shfl_sync(FULL, acc[t].x, kk);
                float by = __shfl_sync(FULL, acc[t].y, kk);
                float bz = __shfl_sync(FULL, acc[t].z, kk);
                float bw = __shfl_sync(FULL, acc[t].w, kk);
                a0[t] += bx * w00 + by * w10 + bz * w20 + bw * w30;
                a1[t] += bx * w01 + by * w11 + bz * w21 + bw * w31;
            }
        }
        #pragma unroll
        for (int t = 0; t < 4; t++) {
            a0[t] = fmaxf(a0[t], 0.f);
            a1[t] = fmaxf(a1[t], 0.f);
        }

        // ---- MLP2 + residual: out = x + hidden @ W2 + b2
        float4 p[4];
        #pragma unroll
        for (int t = 0; t < 4; t++) p[t] = sb2[lane];
        #pragma unroll 8
        for (int jj = 0; jj < 32; jj++) {
            float4 w0 = sW2[jj * 32 + lane];
            float4 w1 = sW2[(jj + 32) * 32 + lane];
            #pragma unroll
            for (int t = 0; t < 4; t++) {
                float u0 = __shfl_sync(FULL, a0[t], jj);
                float u1 = __shfl_sync(FULL, a1[t], jj);
                p[t].x += u0 * w0.x + u1 * w1.x;
                p[t].y += u0 * w0.y + u1 * w1.y;
                p[t].z += u0 * w0.z + u1 * w1.z;
                p[t].w += u0 * w0.w + u1 * w1.w;
            }
        }
        #pragma unroll
        for (int t = 0; t < 4; t++) {
            int n = n0 + t;
            if (n < N) {
                float4 xv = x4[(size_t)n * 32 + lane];
                out4[(size_t)n * 32 + lane] =
                    make_float4(xv.x + p[t].x, xv.y + p[t].y, xv.z + p[t].z, xv.w + p[t].w);
            }
        }
    }
}

// ---------------- launch -------------------------------------------------------
extern "C" void kernel_launch(void* const* d_in, const int* in_sizes, int n_in,
                              void* d_out, int out_size) {
    const float* x    = (const float*)d_in[0];
    const void*  ei   = d_in[1];
    const float* Wsim = (const float*)d_in[2];
    const float* bsim = (const float*)d_in[3];
    const float* wvec = (const float*)d_in[4];
    const float* bvec = (const float*)d_in[5];
    const float* W1   = (const float*)d_in[6];
    const float* b1   = (const float*)d_in[7];
    const float* W2   = (const float*)d_in[8];
    const float* b2   = (const float*)d_in[9];
    float* out = (float*)d_out;

    int N = in_sizes[0] / D;
    int E = in_sizes[1] / 2;
    int nblk = (N + 1023) / 1024;

    static int smem_set = 0;
    int fused_smem = (2 * D * H + H + D) * (int)sizeof(float);  // 66304 B
    if (!smem_set) {
        cudaFuncSetAttribute(k_fused, cudaFuncAttributeMaxDynamicSharedMemorySize, fused_smem);
        smem_set = 1;
    }

    k_detect<<<1, 32>>>(ei, E, N);
    k_zero<<<(N + 255) / 256, 256>>>(N);
    k_gate<<<592, 256>>>((const float4*)x, Wsim, bsim, wvec, bvec, N);
    k_hist<<<2048, 256>>>(ei, E, N);
    k_scan1<<<nblk, 1024>>>(N);
    k_scan2<<<1, 128>>>(nblk, N, E);
    k_scan3<<<nblk, 1024>>>(N);
    k_fill<<<2048, 256>>>(ei, E, N);
    k_fused<<<444, 256, fused_smem>>>((const float4*)x, W1, b1, W2, b2, (float4*)out, N);
}

// round 4
// speedup vs baseline: 1.1261x; 1.1261x over previous
#include <cuda_runtime.h>

#define D 128
#define H 64
#define NMAX 100032
#define EMAX 1600000
#define FULL 0xffffffffu

// ---------------- scratch (static device globals; no allocations) -------------
__device__ float g_weights[NMAX];
__device__ int   g_deg[NMAX];
__device__ int   g_rowoff[NMAX + 1];
__device__ int   g_cursor[NMAX];
__device__ int   g_csrcol[EMAX];
__device__ int   g_partials[256];
__device__ int   g_is64;

// ---------------- dtype detection (1 warp) -------------------------------------
__global__ void k_detect(const void* __restrict__ ei, int E, int N) {
    const long long* e64 = (const long long*)ei;
    int lane = threadIdx.x;
    int ok = 1;
    if (lane < E) {
        long long v = e64[lane];
        ok = (v >= 0 && v < (long long)N) ? 1 : 0;
    }
    unsigned m = __ballot_sync(FULL, ok);
    if (lane == 0) g_is64 = (m == FULL) ? 1 : 0;
}

__device__ __forceinline__ int edge_at(const void* ei, size_t idx, int is64, int N) {
    long long v = is64 ? ((const long long*)ei)[idx] : (long long)((const int*)ei)[idx];
    if (v < 0) v = 0;
    if (v >= N) v = N - 1;
    return (int)v;
}

__global__ void k_zero(int N) {
    int i = blockIdx.x * blockDim.x + threadIdx.x;
    if (i < N) g_deg[i] = 0;
}

// ---------------- gate: weights = sigmoid(tanh(x@Wsim+bsim)@wvec + bvec) ------
__global__ void k_gate(const float4* __restrict__ x4, const float* __restrict__ Wsim,
                       const float* __restrict__ bsim, const float* __restrict__ wvec,
                       const float* __restrict__ bvec, int N) {
    __shared__ float sW[D * H];
    __shared__ float sb[H], sv[H];
    int tid = threadIdx.x;
    for (int i = tid; i < D * H; i += blockDim.x) sW[i] = Wsim[i];
    if (tid < H) { sb[tid] = bsim[tid]; sv[tid] = wvec[tid]; }
    __syncthreads();
    float bv = bvec[0];
    int lane = tid & 31, wp = tid >> 5;
    int gw = blockIdx.x * (blockDim.x >> 5) + wp;
    int nw = gridDim.x * (blockDim.x >> 5);
    int ngroups = (N + 3) >> 2;
    for (int g = gw; g < ngroups; g += nw) {
        int n0 = g * 4;
        float4 xv[4]; float a0[4], a1[4];
        #pragma unroll
        for (int t = 0; t < 4; t++) {
            int n = n0 + t;
            xv[t] = (n < N) ? x4[(size_t)n * 32 + lane] : make_float4(0.f, 0.f, 0.f, 0.f);
            a0[t] = sb[lane]; a1[t] = sb[lane + 32];
        }
        #pragma unroll 8
        for (int kk = 0; kk < 32; kk++) {
            float w00 = sW[(4 * kk + 0) * H + lane], w01 = sW[(4 * kk + 0) * H + lane + 32];
            float w10 = sW[(4 * kk + 1) * H + lane], w11 = sW[(4 * kk + 1) * H + lane + 32];
            float w20 = sW[(4 * kk + 2) * H + lane], w21 = sW[(4 * kk + 2) * H + lane + 32];
            float w30 = sW[(4 * kk + 3) * H + lane], w31 = sW[(4 * kk + 3) * H + lane + 32];
            #pragma unroll
            for (int t = 0; t < 4; t++) {
                float bx = __shfl_sync(FULL, xv[t].x, kk);
                float by = __shfl_sync(FULL, xv[t].y, kk);
                float bz = __shfl_sync(FULL, xv[t].z, kk);
                float bw = __shfl_sync(FULL, xv[t].w, kk);
                a0[t] += bx * w00 + by * w10 + bz * w20 + bw * w30;
                a1[t] += bx * w01 + by * w11 + bz * w21 + bw * w31;
            }
        }
        #pragma unroll
        for (int t = 0; t < 4; t++) {
            float h0 = tanhf(a0[t]), h1 = tanhf(a1[t]);
            float s = h0 * sv[lane] + h1 * sv[lane + 32];
            #pragma unroll
            for (int o = 16; o > 0; o >>= 1) s += __shfl_xor_sync(FULL, s, o);
            if (lane == 0 && n0 + t < N)
                g_weights[n0 + t] = 1.f / (1.f + __expf(-(s + bv)));
        }
    }
}

// ---------------- CSR build ----------------------------------------------------
__global__ void k_hist(const void* __restrict__ ei, int E, int N) {
    int is64 = g_is64;
    int i = blockIdx.x * blockDim.x + threadIdx.x;
    int stride = gridDim.x * blockDim.x;
    for (; i < E; i += stride) atomicAdd(&g_deg[edge_at(ei, i, is64, N)], 1);
}

__global__ void k_scan1(int N) {
    int i = blockIdx.x * 1024 + threadIdx.x;
    int v = (i < N) ? g_deg[i] : 0;
    #pragma unroll
    for (int o = 16; o > 0; o >>= 1) v += __shfl_xor_sync(FULL, v, o);
    __shared__ int ws[32];
    int lane = threadIdx.x & 31, w = threadIdx.x >> 5;
    if (lane == 0) ws[w] = v;
    __syncthreads();
    if (w == 0) {
        int s = ws[lane];
        #pragma unroll
        for (int o = 16; o > 0; o >>= 1) s += __shfl_xor_sync(FULL, s, o);
        if (lane == 0) g_partials[blockIdx.x] = s;
    }
}

__global__ void k_scan2(int nblk, int N, int E) {
    __shared__ int s[128];
    int tid = threadIdx.x;
    int v = (tid < nblk) ? g_partials[tid] : 0;
    s[tid] = v;
    __syncthreads();
    for (int o = 1; o < 128; o <<= 1) {
        int t = 0;
        if (tid >= o) t = s[tid - o];
        __syncthreads();
        s[tid] += t;
        __syncthreads();
    }
    if (tid < nblk) g_partials[tid] = s[tid] - v;
    if (tid == 0) g_rowoff[N] = E;
}

__global__ void k_scan3(int N) {
    int i = blockIdx.x * 1024 + threadIdx.x;
    int lane = threadIdx.x & 31, w = threadIdx.x >> 5;
    int v = (i < N) ? g_deg[i] : 0;
    int s = v;
    #pragma unroll
    for (int o = 1; o < 32; o <<= 1) {
        int t = __shfl_up_sync(FULL, s, o);
        if (lane >= o) s += t;
    }
    __shared__ int ws[32];
    if (lane == 31) ws[w] = s;
    __syncthreads();
    if (w == 0) {
        int t2 = ws[lane];
        #pragma unroll
        for (int o = 1; o < 32; o <<= 1) {
            int u = __shfl_up_sync(FULL, t2, o);
            if (lane >= o) t2 += u;
        }
        ws[lane] = t2;
    }
    __syncthreads();
    int excl = s - v + ((w > 0) ? ws[w - 1] : 0) + g_partials[blockIdx.x];
    if (i < N) { g_rowoff[i] = excl; g_cursor[i] = excl; }
}

__global__ void k_fill(const void* __restrict__ ei, int E, int N) {
    int is64 = g_is64;
    int i = blockIdx.x * blockDim.x + threadIdx.x;
    int stride = gridDim.x * blockDim.x;
    for (; i < E; i += stride) {
        int r = edge_at(ei, i, is64, N);
        int c = edge_at(ei, (size_t)E + i, is64, N);
        int pos = atomicAdd(&g_cursor[r], 1);
        if (pos >= 0 && pos < EMAX) g_csrcol[pos] = c;
    }
}

// ---------------- FUSED: gather + MLP1 + MLP2 + residual -----------------------
__global__ void k_fused(const float4* __restrict__ x4,
                        const float* __restrict__ W1, const float* __restrict__ b1,
                        const float* __restrict__ W2, const float* __restrict__ b2,
                        float4* __restrict__ out4, int N) {
    extern __shared__ float sm[];
    float*  sW1 = sm;                                  // [D*H]
    float4* sW2 = (float4*)(sm + D * H);               // [H*32] float4
    float*  sb1 = sm + 2 * D * H;                      // [64]
    float4* sb2 = (float4*)(sm + 2 * D * H + H);       // [32] float4

    int tid = threadIdx.x;
    for (int i = tid; i < D * H; i += blockDim.x) sW1[i] = W1[i];
    float* sW2f = (float*)sW2;
    for (int i = tid; i < H * D; i += blockDim.x) sW2f[i] = W2[i];
    if (tid < H) sb1[tid] = b1[tid];
    if (tid < 32) sb2[tid] = ((const float4*)b2)[tid];
    __syncthreads();

    int lane = tid & 31, wp = tid >> 5;
    int gw = blockIdx.x * (blockDim.x >> 5) + wp;
    int nw = gridDim.x * (blockDim.x >> 5);
    int ngroups = (N + 3) >> 2;

    for (int g = gw; g < ngroups; g += nw) {
        int n0 = g * 4;

        // ---- gather: acc[t] = sum_{edges of node n0+t} w[col] * x[col]
        float4 acc[4];
        #pragma unroll
        for (int t = 0; t < 4; t++) {
            acc[t] = make_float4(0.f, 0.f, 0.f, 0.f);
            int n = n0 + t;
            if (n >= N) continue;
            int s = g_rowoff[n], e = g_rowoff[n + 1];
            int p = s;
            // 8-wide unroll: ~24 outstanding loads per warp to hide L2 latency
            for (; p + 8 <= e; p += 8) {
                int   c[8]; float wv[8]; float4 v[8];
                #pragma unroll
                for (int q = 0; q < 8; q++) c[q] = g_csrcol[p + q];
                #pragma unroll
                for (int q = 0; q < 8; q++) wv[q] = g_weights[c[q]];
                #pragma unroll
                for (int q = 0; q < 8; q++) v[q] = x4[(size_t)c[q] * 32 + lane];
                #pragma unroll
                for (int q = 0; q < 8; q++) {
                    acc[t].x += v[q].x * wv[q];
                    acc[t].y += v[q].y * wv[q];
                    acc[t].z += v[q].z * wv[q];
                    acc[t].w += v[q].w * wv[q];
                }
            }
            for (; p < e; p++) {
                int cc = g_csrcol[p];
                float w = g_weights[cc];
                float4 v = x4[(size_t)cc * 32 + lane];
                acc[t].x += v.x * w; acc[t].y += v.y * w;
                acc[t].z += v.z * w; acc[t].w += v.w * w;
            }
        }

        // ---- MLP1: h = relu(readout @ W1 + b1); per lane a0=h[lane], a1=h[lane+32]
        float a0[4], a1[4];
        #pragma unroll
        for (int t = 0; t < 4; t++) { a0[t] = sb1[lane]; a1[t] = sb1[lane + 32]; }
        #pragma unroll 8
        for (int kk = 0; kk < 32; kk++) {
            float w00 = sW1[(4 * kk + 0) * H + lane], w01 = sW1[(4 * kk + 0) * H + lane + 32];
            float w10 = sW1[(4 * kk + 1) * H + lane], w11 = sW1[(4 * kk + 1) * H + lane + 32];
            float w20 = sW1[(4 * kk + 2) * H + lane], w21 = sW1[(4 * kk + 2) * H + lane + 32];
            float w30 = sW1[(4 * kk + 3) * H + lane], w31 = sW1[(4 * kk + 3) * H + lane + 32];
            #pragma unroll
            for (int t = 0; t < 4; t++) {
                float bx = __shfl_sync(FULL, acc[t].x, kk);
                float by = __shfl_sync(FULL, acc[t].y, kk);
                float bz = __shfl_sync(FULL, acc[t].z, kk);
                float bw = __shfl_sync(FULL, acc[t].w, kk);
                a0[t] += bx * w00 + by * w10 + bz * w20 + bw * w30;
                a1[t] += bx * w01 + by * w11 + bz * w21 + bw * w31;
            }
        }
        #pragma unroll
        for (int t = 0; t < 4; t++) {
            a0[t] = fmaxf(a0[t], 0.f);
            a1[t] = fmaxf(a1[t], 0.f);
        }

        // ---- MLP2 + residual
        float4 p[4];
        #pragma unroll
        for (int t = 0; t < 4; t++) p[t] = sb2[lane];
        #pragma unroll 8
        for (int jj = 0; jj < 32; jj++) {
            float4 w0 = sW2[jj * 32 + lane];
            float4 w1 = sW2[(jj + 32) * 32 + lane];
            #pragma unroll
            for (int t = 0; t < 4; t++) {
                float u0 = __shfl_sync(FULL, a0[t], jj);
                float u1 = __shfl_sync(FULL, a1[t], jj);
                p[t].x += u0 * w0.x + u1 * w1.x;
                p[t].y += u0 * w0.y + u1 * w1.y;
                p[t].z += u0 * w0.z + u1 * w1.z;
                p[t].w += u0 * w0.w + u1 * w1.w;
            }
        }
        #pragma unroll
        for (int t = 0; t < 4; t++) {
            int n = n0 + t;
            if (n < N) {
                float4 xv = x4[(size_t)n * 32 + lane];
                out4[(size_t)n * 32 + lane] =
                    make_float4(xv.x + p[t].x, xv.y + p[t].y, xv.z + p[t].z, xv.w + p[t].w);
            }
        }
    }
}

// ---------------- launch -------------------------------------------------------
extern "C" void kernel_launch(void* const* d_in, const int* in_sizes, int n_in,
                              void* d_out, int out_size) {
    const float* x    = (const float*)d_in[0];
    const void*  ei   = d_in[1];
    const float* Wsim = (const float*)d_in[2];
    const float* bsim = (const float*)d_in[3];
    const float* wvec = (const float*)d_in[4];
    const float* bvec = (const float*)d_in[5];
    const float* W1   = (const float*)d_in[6];
    const float* b1   = (const float*)d_in[7];
    const float* W2   = (const float*)d_in[8];
    const float* b2   = (const float*)d_in[9];
    float* out = (float*)d_out;

    int N = in_sizes[0] / D;
    int E = in_sizes[1] / 2;
    int nblk = (N + 1023) / 1024;

    static int inited = 0;
    static cudaStream_t s2;
    static cudaEvent_t evFork, evJoin;
    int fused_smem = (2 * D * H + H + D) * (int)sizeof(float);  // 66304 B
    if (!inited) {
        cudaStreamCreateWithFlags(&s2, cudaStreamNonBlocking);
        cudaEventCreateWithFlags(&evFork, cudaEventDisableTiming);
        cudaEventCreateWithFlags(&evJoin, cudaEventDisableTiming);
        cudaFuncSetAttribute(k_fused, cudaFuncAttributeMaxDynamicSharedMemorySize, fused_smem);
        inited = 1;
    }

    // fork: CSR build chain runs on s2 concurrently with the gate GEMM on stream 0
    cudaEventRecord(evFork, 0);
    cudaStreamWaitEvent(s2, evFork, 0);

    // stream 0: gate (needs only x + small weights)
    k_gate<<<592, 256>>>((const float4*)x, Wsim, bsim, wvec, bvec, N);

    // stream s2: CSR build (needs only edge_index)
    k_detect<<<1, 32, 0, s2>>>(ei, E, N);
    k_zero<<<(N + 255) / 256, 256, 0, s2>>>(N);
    k_hist<<<2048, 256, 0, s2>>>(ei, E, N);
    k_scan1<<<nblk, 1024, 0, s2>>>(N);
    k_scan2<<<1, 128, 0, s2>>>(nblk, N, E);
    k_scan3<<<nblk, 1024, 0, s2>>>(N);
    k_fill<<<2048, 256, 0, s2>>>(ei, E, N);

    // join
    cudaEventRecord(evJoin, s2);
    cudaStreamWaitEvent(0, evJoin, 0);

    k_fused<<<444, 256, fused_smem>>>((const float4*)x, W1, b1, W2, b2, (float4*)out, N);
}